// round 1
// baseline (speedup 1.0000x reference)
#include <cuda_runtime.h>

#define Cc 10
#define Bb 512
#define Nn 1152
#define Ii 8
#define Oo 16

// Scratch for u_hat[C,B,N,O] — 94,371,840 floats = 377 MB (static device array: allowed).
__device__ float g_uhat[Cc * Bb * Nn * Oo];

// ---------------------------------------------------------------------------
// Phase 1: u_hat[c,b,n,o] = sum_i u[b,n,i] * W[c,n,i,o]
// Block: 256 threads = 128 n-positions x 2 o-halves. Each thread holds
// W[c,n,:,half*8:half*8+8] (64 regs) and loops over 64 batches.
// Grid: (N/128=9, B/64=8, C=10)
// ---------------------------------------------------------------------------
__global__ __launch_bounds__(256) void uhat_kernel(const float* __restrict__ u,
                                                   const float* __restrict__ W) {
    const int tid  = threadIdx.x;
    const int n    = blockIdx.x * 128 + (tid >> 1);
    const int half = tid & 1;
    const int b0   = blockIdx.y * 64;
    const int c    = blockIdx.z;

    // Load W[c,n,:, half*8 .. half*8+7] into registers: w[i][o]
    float w[8][8];
    const float* Wp = W + (((size_t)c * Nn + n) * Ii) * Oo + half * 8;
#pragma unroll
    for (int i = 0; i < 8; i++) {
        float4 a = *(const float4*)(Wp + i * Oo);
        float4 b = *(const float4*)(Wp + i * Oo + 4);
        w[i][0] = a.x; w[i][1] = a.y; w[i][2] = a.z; w[i][3] = a.w;
        w[i][4] = b.x; w[i][5] = b.y; w[i][6] = b.z; w[i][7] = b.w;
    }

    const float* ub = u + ((size_t)b0 * Nn + n) * Ii;
    float* ob = g_uhat + (((size_t)c * Bb + b0) * Nn + n) * Oo + half * 8;

    for (int j = 0; j < 64; j++) {
        const float* up = ub + (size_t)j * (Nn * Ii);
        float4 u0 = __ldg((const float4*)up);
        float4 u1 = __ldg((const float4*)(up + 4));
        float us[8] = {u0.x, u0.y, u0.z, u0.w, u1.x, u1.y, u1.z, u1.w};

        float acc[8];
#pragma unroll
        for (int o = 0; o < 8; o++) acc[o] = us[0] * w[0][o];
#pragma unroll
        for (int i = 1; i < 8; i++) {
#pragma unroll
            for (int o = 0; o < 8; o++) acc[o] = fmaf(us[i], w[i][o], acc[o]);
        }

        float* op = ob + (size_t)j * (Nn * Oo);
        float4 r0 = make_float4(acc[0], acc[1], acc[2], acc[3]);
        float4 r1 = make_float4(acc[4], acc[5], acc[6], acc[7]);
        __stcs((float4*)op, r0);
        __stcs((float4*)(op + 4), r1);
    }
}

// ---------------------------------------------------------------------------
// Phase 2: dynamic routing, one 128-thread CTA per (c,b).
// Each thread owns 9 interleaved rows of u_hat[c,b] in registers (144 f32).
// Routing identity: logits at iter k are u_hat[n] . (v1 + ... + v_{k-1}),
// so each iteration is one register pass with unnormalized softmax.
// Grid: (B=512, C=10)
// ---------------------------------------------------------------------------
__global__ __launch_bounds__(128) void routing_kernel(float* __restrict__ out) {
    const int tid  = threadIdx.x;
    const int b    = blockIdx.x;
    const int c    = blockIdx.y;
    const int lane = tid & 31;
    const int wid  = tid >> 5;

    __shared__ float red[4][17];  // per-warp partials: S[16], z
    __shared__ float Vs[16];      // accumulated v (v1 + v2 ...)

    // Load this thread's 9 rows (interleaved by 128 for coalescing).
    float uh[9][16];
    const float4* p =
        (const float4*)(g_uhat + (((size_t)c * Bb + b) * Nn) * (size_t)Oo);
#pragma unroll
    for (int r = 0; r < 9; r++) {
#pragma unroll
        for (int k = 0; k < 4; k++) {
            float4 v = __ldcs(p + (size_t)(tid + r * 128) * 4 + k);
            uh[r][k * 4 + 0] = v.x;
            uh[r][k * 4 + 1] = v.y;
            uh[r][k * 4 + 2] = v.z;
            uh[r][k * 4 + 3] = v.w;
        }
    }

    float Vr[16];  // register copy of accumulated V (valid for it >= 1)

    for (int it = 0; it < 3; it++) {
        float S[16];
        float z;
        if (it == 0) {
            // uniform weights (softmax of zeros): weight 1 per row, Z = N
            z = 9.0f;  // rows per thread
#pragma unroll
            for (int o = 0; o < 16; o++) S[o] = 0.0f;
#pragma unroll
            for (int r = 0; r < 9; r++) {
#pragma unroll
                for (int o = 0; o < 16; o++) S[o] += uh[r][o];
            }
        } else {
            z = 0.0f;
#pragma unroll
            for (int o = 0; o < 16; o++) S[o] = 0.0f;
#pragma unroll
            for (int r = 0; r < 9; r++) {
                float a = 0.0f;
#pragma unroll
                for (int o = 0; o < 16; o++) a = fmaf(uh[r][o], Vr[o], a);
                float e = __expf(a);
                z += e;
#pragma unroll
                for (int o = 0; o < 16; o++) S[o] = fmaf(e, uh[r][o], S[o]);
            }
        }

        // Warp tree-reduce z and S[16]
#pragma unroll
        for (int off = 16; off > 0; off >>= 1) {
            z += __shfl_xor_sync(0xffffffffu, z, off);
#pragma unroll
            for (int o = 0; o < 16; o++)
                S[o] += __shfl_xor_sync(0xffffffffu, S[o], off);
        }
        if (lane == 0) {
#pragma unroll
            for (int o = 0; o < 16; o++) red[wid][o] = S[o];
            red[wid][16] = z;
        }
        __syncthreads();

        if (tid == 0) {
            float Z = red[0][16] + red[1][16] + red[2][16] + red[3][16];
            float inv = 1.0f / Z;
            float s[16];
            float sn = 0.0f;
#pragma unroll
            for (int o = 0; o < 16; o++) {
                s[o] = (red[0][o] + red[1][o] + red[2][o] + red[3][o]) * inv;
                sn = fmaf(s[o], s[o], sn);
            }
            // squash: (sn/(1+sn)) * s/sqrt(sn)
            float f = (sn / (1.0f + sn)) * rsqrtf(sn);
            if (it < 2) {
#pragma unroll
                for (int o = 0; o < 16; o++) {
                    float v = s[o] * f;
                    Vs[o] = (it == 0) ? v : (Vs[o] + v);
                }
            } else {
                float* op = out + ((size_t)c * Bb + b) * Oo;
#pragma unroll
                for (int o = 0; o < 16; o++) op[o] = s[o] * f;
            }
        }
        __syncthreads();
        if (it < 2) {
#pragma unroll
            for (int o = 0; o < 16; o++) Vr[o] = Vs[o];
        }
        __syncthreads();
    }
}

// ---------------------------------------------------------------------------
extern "C" void kernel_launch(void* const* d_in, const int* in_sizes, int n_in,
                              void* d_out, int out_size) {
    const float* u = (const float*)d_in[0];  // [B,N,I]
    const float* W = (const float*)d_in[1];  // [C,N,I,O]
    float* out = (float*)d_out;              // [C,B,1,1,O]

    uhat_kernel<<<dim3(Nn / 128, Bb / 64, Cc), 256>>>(u, W);
    routing_kernel<<<dim3(Bb, Cc), 128>>>(out);
}

// round 3
// speedup vs baseline: 1.0735x; 1.0735x over previous
#include <cuda_runtime.h>

#define Cc 10
#define Bb 512
#define Nn 1152
#define Ii 8
#define Oo 16
#define BT 16  // batch tile per phase-1 CTA

// Scratch u_hat[C,B,N,O] = 377 MB
__device__ float g_uhat[(size_t)Cc * Bb * Nn * Oo];

typedef unsigned long long u64;

// ---- packed f32x2 helpers (Blackwell; ptxas never auto-fuses these) ----
__device__ __forceinline__ u64 fma2(u64 a, u64 b, u64 c) {
    u64 d; asm("fma.rn.f32x2 %0, %1, %2, %3;" : "=l"(d) : "l"(a), "l"(b), "l"(c)); return d;
}
__device__ __forceinline__ u64 mul2(u64 a, u64 b) {
    u64 d; asm("mul.rn.f32x2 %0, %1, %2;" : "=l"(d) : "l"(a), "l"(b)); return d;
}
__device__ __forceinline__ u64 add2(u64 a, u64 b) {
    u64 d; asm("add.rn.f32x2 %0, %1, %2;" : "=l"(d) : "l"(a), "l"(b)); return d;
}
__device__ __forceinline__ u64 dup2(float x) {
    u64 d; asm("mov.b64 %0, {%1, %1};" : "=l"(d) : "f"(x)); return d;
}
__device__ __forceinline__ u64 pack2(float lo, float hi) {
    u64 d; asm("mov.b64 %0, {%1, %2};" : "=l"(d) : "f"(lo), "f"(hi)); return d;
}
__device__ __forceinline__ void unpack2(u64 a, float& lo, float& hi) {
    asm("mov.b64 {%0, %1}, %2;" : "=f"(lo), "=f"(hi) : "l"(a));
}

// ---------------------------------------------------------------------------
// Phase 1: u_hat[c,b,n,o] = sum_i u[b,n,i] * W[c,n,i,o]
// Block: 256 thr = 128 n x 2 o-halves. u tile [BT x 128 x 8] staged in SMEM
// once; c loops INSIDE the block (u DRAM read = 1x total). Packed f32x2 FMA.
// Grid: (N/128 = 9, B/BT = 32)
// ---------------------------------------------------------------------------
__global__ __launch_bounds__(256) void uhat_kernel(const float* __restrict__ u,
                                                   const float* __restrict__ W) {
    extern __shared__ float us[];  // BT*128*8 floats = 64 KB
    const int tid = threadIdx.x;
    const int n0  = blockIdx.x * 128;
    const int b0  = blockIdx.y * BT;

    // Stage u[b0:b0+BT, n0:n0+128, :] -> SMEM (coalesced float4)
#pragma unroll
    for (int f = tid; f < BT * 256; f += 256) {
        int j = f >> 8, rem = f & 255;
        int nn = rem >> 1, q = rem & 1;
        float4 v = *(const float4*)(u + ((size_t)(b0 + j) * Nn + n0 + nn) * Ii + q * 4);
        ((float4*)us)[f] = v;
    }
    __syncthreads();

    const int n = tid >> 1, h = tid & 1;
    const float* wbase = W + ((size_t)(n0 + n) * Ii) * Oo + h * 8;

    for (int c = 0; c < Cc; c++) {
        // W[c, n0+n, i, 8h..8h+7] as packed pairs
        u64 w2[8][4];
        const float* wc = wbase + (size_t)c * Nn * Ii * Oo;
#pragma unroll
        for (int i = 0; i < 8; i++) {
            ulonglong2 aa = *(const ulonglong2*)(wc + i * Oo);
            ulonglong2 bb = *(const ulonglong2*)(wc + i * Oo + 4);
            w2[i][0] = aa.x; w2[i][1] = aa.y; w2[i][2] = bb.x; w2[i][3] = bb.y;
        }
        float* ob = g_uhat + (((size_t)c * Bb + b0) * Nn + n0 + n) * Oo + h * 8;
#pragma unroll 4
        for (int j = 0; j < BT; j++) {
            const float4* up = (const float4*)(us + ((size_t)j * 128 + n) * Ii);
            float4 a = up[0], b = up[1];
            float usv[8] = {a.x, a.y, a.z, a.w, b.x, b.y, b.z, b.w};
            u64 acc[4];
            {
                u64 ud = dup2(usv[0]);
#pragma unroll
                for (int k = 0; k < 4; k++) acc[k] = mul2(ud, w2[0][k]);
            }
#pragma unroll
            for (int i = 1; i < 8; i++) {
                u64 ud = dup2(usv[i]);
#pragma unroll
                for (int k = 0; k < 4; k++) acc[k] = fma2(ud, w2[i][k], acc[k]);
            }
            float r[8];
#pragma unroll
            for (int k = 0; k < 4; k++) unpack2(acc[k], r[2 * k], r[2 * k + 1]);
            float* op = ob + (size_t)j * (Nn * Oo);
            __stcs((float4*)op, make_float4(r[0], r[1], r[2], r[3]));
            __stcs((float4*)(op + 4), make_float4(r[4], r[5], r[6], r[7]));
        }
    }
}

// ---------------------------------------------------------------------------
// Phase 2: routing. 256-thr CTA per (c,b); thread = (n-lane 0..127, o-half).
// Each thread holds 9 rows x 8 o in packed f32x2 regs (72 f32 regs of data).
// Logit dot completed via shfl_xor(.,1) with the partner half.
// Walks (c,b) in reverse phase-1 write order to catch the L2-resident tail.
// Grid: (B, C)
// ---------------------------------------------------------------------------
__global__ __launch_bounds__(256, 2) void routing_kernel(float* __restrict__ out) {
    const int tid  = threadIdx.x;
    const int b    = (Bb - 1) - blockIdx.x;
    const int c    = (Cc - 1) - blockIdx.y;
    const int lane = tid & 31, wid = tid >> 5;
    const int nl   = tid >> 1, h = tid & 1;

    __shared__ float red[8][2][12];  // [warp][half][S0..7, z]
    __shared__ float Vs[16];         // accumulated v

    // Load u_hat slab: 9 rows x 8 floats per thread, packed pairs
    u64 uh[9][4];
    const longlong2* p =
        (const longlong2*)(g_uhat + ((size_t)c * Bb + b) * (size_t)(Nn * Oo));
#pragma unroll
    for (int r = 0; r < 9; r++) {
        size_t base = (size_t)(r * 128 + nl) * 4 + h * 2;  // ulonglong2 units
        longlong2 t0 = __ldcs(p + base);
        longlong2 t1 = __ldcs(p + base + 1);
        uh[r][0] = (u64)t0.x; uh[r][1] = (u64)t0.y;
        uh[r][2] = (u64)t1.x; uh[r][3] = (u64)t1.y;
    }

    for (int it = 0; it < 3; it++) {
        float S[8], z;
        if (it == 0) {
            u64 S2[4] = {0ull, 0ull, 0ull, 0ull};
#pragma unroll
            for (int r = 0; r < 9; r++)
#pragma unroll
                for (int k = 0; k < 4; k++) S2[k] = add2(S2[k], uh[r][k]);
#pragma unroll
            for (int k = 0; k < 4; k++) unpack2(S2[k], S[2 * k], S[2 * k + 1]);
            z = 9.0f;  // 9 rows, unit weight
        } else {
            u64 V2[4];
#pragma unroll
            for (int k = 0; k < 4; k++)
                V2[k] = pack2(Vs[8 * h + 2 * k], Vs[8 * h + 2 * k + 1]);
            float a[9];
#pragma unroll
            for (int r = 0; r < 9; r++) {
                u64 d = mul2(uh[r][0], V2[0]);
                d = fma2(uh[r][1], V2[1], d);
                d = fma2(uh[r][2], V2[2], d);
                d = fma2(uh[r][3], V2[3], d);
                float lo, hi; unpack2(d, lo, hi);
                a[r] = lo + hi;
            }
#pragma unroll
            for (int r = 0; r < 9; r++)
                a[r] += __shfl_xor_sync(0xffffffffu, a[r], 1);  // partner half
            float e[9];
#pragma unroll
            for (int r = 0; r < 9; r++) e[r] = __expf(a[r]);
            z = 0.0f;
            u64 S2[4] = {0ull, 0ull, 0ull, 0ull};
#pragma unroll
            for (int r = 0; r < 9; r++) {
                z += e[r];
                u64 ed = dup2(e[r]);
#pragma unroll
                for (int k = 0; k < 4; k++) S2[k] = fma2(ed, uh[r][k], S2[k]);
            }
#pragma unroll
            for (int k = 0; k < 4; k++) unpack2(S2[k], S[2 * k], S[2 * k + 1]);
        }

        // Reduce over the 16 same-half lanes of each warp (xor 2,4,8,16)
#pragma unroll
        for (int off = 2; off <= 16; off <<= 1) {
            z += __shfl_xor_sync(0xffffffffu, z, off);
#pragma unroll
            for (int o = 0; o < 8; o++)
                S[o] += __shfl_xor_sync(0xffffffffu, S[o], off);
        }
        if (lane < 2) {  // lane 0 = half 0, lane 1 = half 1
#pragma unroll
            for (int o = 0; o < 8; o++) red[wid][lane][o] = S[o];
            red[wid][lane][8] = z;
        }
        __syncthreads();

        // Final combine + squash: 16 threads, one per o
        if (tid < 16) {
            int o = tid, hh = o >> 3, k = o & 7;
            float s = 0.0f, Z = 0.0f;
#pragma unroll
            for (int w = 0; w < 8; w++) { s += red[w][hh][k]; Z += red[w][0][8]; }
            s /= Z;
            float sn = s * s;
#pragma unroll
            for (int off = 1; off <= 8; off <<= 1)
                sn += __shfl_xor_sync(0xffffu, sn, off);
            float fq = (sn / (1.0f + sn)) * rsqrtf(sn);
            float v = s * fq;
            if (it == 2) out[((size_t)c * Bb + b) * Oo + o] = v;
            else Vs[o] = (it == 0) ? v : (Vs[o] + v);
        }
        __syncthreads();
    }
}

// ---------------------------------------------------------------------------
extern "C" void kernel_launch(void* const* d_in, const int* in_sizes, int n_in,
                              void* d_out, int out_size) {
    const float* u = (const float*)d_in[0];  // [B,N,I]
    const float* W = (const float*)d_in[1];  // [C,N,I,O]
    float* out = (float*)d_out;              // [C,B,1,1,O]

    const int smem = BT * 128 * 8 * sizeof(float);  // 64 KB
    cudaFuncSetAttribute(uhat_kernel, cudaFuncAttributeMaxDynamicSharedMemorySize, smem);
    uhat_kernel<<<dim3(Nn / 128, Bb / BT), 256, smem>>>(u, W);
    routing_kernel<<<dim3(Bb, Cc), 256>>>(out);
}

// round 6
// speedup vs baseline: 1.7252x; 1.6071x over previous
#include <cuda_runtime.h>
#include <cuda_fp16.h>

#define Cc 10
#define Bb 512
#define Nn 1152
#define Ii 8
#define Oo 16

// Scratch u_hat[C,B,N,O] in fp16, stored as uint4 (8 halves per uint4) = 189 MB
__device__ uint4 g_uhat[(size_t)Cc * Bb * Nn * Oo / 8];

typedef unsigned long long u64;

// ---- packed f32x2 helpers (ptxas never auto-fuses these from C++) ----
__device__ __forceinline__ u64 fma2(u64 a, u64 b, u64 c) {
    u64 d; asm("fma.rn.f32x2 %0, %1, %2, %3;" : "=l"(d) : "l"(a), "l"(b), "l"(c)); return d;
}
__device__ __forceinline__ u64 mul2(u64 a, u64 b) {
    u64 d; asm("mul.rn.f32x2 %0, %1, %2;" : "=l"(d) : "l"(a), "l"(b)); return d;
}
__device__ __forceinline__ u64 add2(u64 a, u64 b) {
    u64 d; asm("add.rn.f32x2 %0, %1, %2;" : "=l"(d) : "l"(a), "l"(b)); return d;
}
__device__ __forceinline__ u64 dup2(float x) {
    u64 d; asm("mov.b64 %0, {%1, %1};" : "=l"(d) : "f"(x)); return d;
}
__device__ __forceinline__ u64 pack2(float lo, float hi) {
    u64 d; asm("mov.b64 %0, {%1, %2};" : "=l"(d) : "f"(lo), "f"(hi)); return d;
}
__device__ __forceinline__ void unpack2(u64 a, float& lo, float& hi) {
    asm("mov.b64 {%0, %1}, %2;" : "=f"(lo), "=f"(hi) : "l"(a));
}
// pack two f32 into one f16x2 word (lo -> lower half, hi -> upper half)
__device__ __forceinline__ unsigned cvth2(float lo, float hi) {
    __half2 h = __floats2half2_rn(lo, hi);
    return *(unsigned*)&h;
}
// f16x2 word -> packed f32x2 (lower half -> lo f32, upper half -> hi f32)
__device__ __forceinline__ u64 h2f2(unsigned w) {
    __half2 h = *(__half2*)&w;
    float2 f = __half22float2(h);
    return pack2(f.x, f.y);
}

// ---------------------------------------------------------------------------
// Phase 1: u_hat[c,b,n,o] = sum_i u[b,n,i] * W[c,n,i,o], stored fp16.
// 256 thr = 128 n x 2 o-halves. W[c,n,:,8h..8h+7] in 64 regs; 64-batch loop.
// u (18.9 MB) stays L2-resident across the 10 c-slices. One STG.128 per j.
// Grid: (N/128 = 9, B/64 = 8, C = 10) = 720 CTAs, no smem (high occupancy).
// ---------------------------------------------------------------------------
__global__ __launch_bounds__(256) void uhat_kernel(const float* __restrict__ u,
                                                   const float* __restrict__ W) {
    const int tid = threadIdx.x;
    const int n   = blockIdx.x * 128 + (tid >> 1);
    const int h   = tid & 1;
    const int b0  = blockIdx.y * 64;
    const int c   = blockIdx.z;

    // W[c,n,i, 8h..8h+7] as packed f32 pairs
    u64 w2[8][4];
    const float* wc = W + (((size_t)c * Nn + n) * Ii) * Oo + h * 8;
#pragma unroll
    for (int i = 0; i < 8; i++) {
        ulonglong2 aa = *(const ulonglong2*)(wc + i * Oo);
        ulonglong2 bb = *(const ulonglong2*)(wc + i * Oo + 4);
        w2[i][0] = aa.x; w2[i][1] = aa.y; w2[i][2] = bb.x; w2[i][3] = bb.y;
    }

    const float* ub = u + ((size_t)b0 * Nn + n) * Ii;
    uint4* ob = g_uhat + (((size_t)c * Bb + b0) * Nn + n) * 2 + h;

#pragma unroll 4
    for (int j = 0; j < 64; j++) {
        const float4* up = (const float4*)(ub + (size_t)j * (Nn * Ii));
        float4 a = __ldg(up);
        float4 b = __ldg(up + 1);
        float usv[8] = {a.x, a.y, a.z, a.w, b.x, b.y, b.z, b.w};

        u64 acc[4];
        {
            u64 ud = dup2(usv[0]);
#pragma unroll
            for (int k = 0; k < 4; k++) acc[k] = mul2(ud, w2[0][k]);
        }
#pragma unroll
        for (int i = 1; i < 8; i++) {
            u64 ud = dup2(usv[i]);
#pragma unroll
            for (int k = 0; k < 4; k++) acc[k] = fma2(ud, w2[i][k], acc[k]);
        }
        float r[8];
#pragma unroll
        for (int k = 0; k < 4; k++) unpack2(acc[k], r[2 * k], r[2 * k + 1]);

        uint4 st;
        st.x = cvth2(r[0], r[1]);
        st.y = cvth2(r[2], r[3]);
        st.z = cvth2(r[4], r[5]);
        st.w = cvth2(r[6], r[7]);
        __stcs(ob + (size_t)j * (Nn * 2), st);
    }
}

// ---------------------------------------------------------------------------
// Phase 2: routing. 256-thr CTA per (c,b); thread = (n-lane 0..127, o-half).
// 9 rows x 8 o per thread, converted fp16 -> packed f32x2 (72 f32 data regs).
// Logits: u_hat[n].(v1+..+v_{k-1}) => unnormalized softmax, 1 pass per iter.
// Walks (c,b) in reverse write order to catch the L2-resident tail.
// Grid: (B, C)
// ---------------------------------------------------------------------------
__global__ __launch_bounds__(256, 2) void routing_kernel(float* __restrict__ out) {
    const int tid  = threadIdx.x;
    const int b    = (Bb - 1) - blockIdx.x;
    const int c    = (Cc - 1) - blockIdx.y;
    const int lane = tid & 31, wid = tid >> 5;
    const int nl   = tid >> 1, h = tid & 1;

    __shared__ float red[8][2][12];  // [warp][half][S0..7, z]
    __shared__ float Vs[16];         // accumulated v

    // Load slab: one uint4 (8 fp16) per row per thread, fully coalesced.
    u64 uh[9][4];
    const uint4* p = g_uhat + ((size_t)c * Bb + b) * (size_t)(Nn * 2);
#pragma unroll
    for (int r = 0; r < 9; r++) {
        uint4 t = __ldcs(p + (size_t)(r * 128 + nl) * 2 + h);
        uh[r][0] = h2f2(t.x);
        uh[r][1] = h2f2(t.y);
        uh[r][2] = h2f2(t.z);
        uh[r][3] = h2f2(t.w);
    }

    for (int it = 0; it < 3; it++) {
        float S[8], z;
        if (it == 0) {
            u64 S2[4] = {0ull, 0ull, 0ull, 0ull};
#pragma unroll
            for (int r = 0; r < 9; r++)
#pragma unroll
                for (int k = 0; k < 4; k++) S2[k] = add2(S2[k], uh[r][k]);
#pragma unroll
            for (int k = 0; k < 4; k++) unpack2(S2[k], S[2 * k], S[2 * k + 1]);
            z = 9.0f;  // 9 rows, unit weight
        } else {
            u64 V2[4];
#pragma unroll
            for (int k = 0; k < 4; k++)
                V2[k] = pack2(Vs[8 * h + 2 * k], Vs[8 * h + 2 * k + 1]);
            float a[9];
#pragma unroll
            for (int r = 0; r < 9; r++) {
                u64 d = mul2(uh[r][0], V2[0]);
                d = fma2(uh[r][1], V2[1], d);
                d = fma2(uh[r][2], V2[2], d);
                d = fma2(uh[r][3], V2[3], d);
                float lo, hi; unpack2(d, lo, hi);
                a[r] = lo + hi;
            }
#pragma unroll
            for (int r = 0; r < 9; r++)
                a[r] += __shfl_xor_sync(0xffffffffu, a[r], 1);  // partner half
            float e[9];
#pragma unroll
            for (int r = 0; r < 9; r++) e[r] = __expf(a[r]);
            z = 0.0f;
            u64 S2[4] = {0ull, 0ull, 0ull, 0ull};
#pragma unroll
            for (int r = 0; r < 9; r++) {
                z += e[r];
                u64 ed = dup2(e[r]);
#pragma unroll
                for (int k = 0; k < 4; k++) S2[k] = fma2(ed, uh[r][k], S2[k]);
            }
#pragma unroll
            for (int k = 0; k < 4; k++) unpack2(S2[k], S[2 * k], S[2 * k + 1]);
        }

        // Reduce over the 16 same-half lanes of each warp (xor 2,4,8,16)
#pragma unroll
        for (int off = 2; off <= 16; off <<= 1) {
            z += __shfl_xor_sync(0xffffffffu, z, off);
#pragma unroll
            for (int o = 0; o < 8; o++)
                S[o] += __shfl_xor_sync(0xffffffffu, S[o], off);
        }
        if (lane < 2) {  // lane 0 = half 0, lane 1 = half 1
#pragma unroll
            for (int o = 0; o < 8; o++) red[wid][lane][o] = S[o];
            red[wid][lane][8] = z;
        }
        __syncthreads();

        // Final combine + squash: 16 threads, one per o
        if (tid < 16) {
            int o = tid, hh = o >> 3, k = o & 7;
            float s = 0.0f, Z = 0.0f;
#pragma unroll
            for (int w = 0; w < 8; w++) { s += red[w][hh][k]; Z += red[w][0][8]; }
            s /= Z;
            float sn = s * s;
#pragma unroll
            for (int off = 1; off <= 8; off <<= 1)
                sn += __shfl_xor_sync(0xffffu, sn, off);
            float fq = (sn / (1.0f + sn)) * rsqrtf(sn);
            float v = s * fq;
            if (it == 2) out[((size_t)c * Bb + b) * Oo + o] = v;
            else Vs[o] = (it == 0) ? v : (Vs[o] + v);
        }
        __syncthreads();
    }
}

// ---------------------------------------------------------------------------
extern "C" void kernel_launch(void* const* d_in, const int* in_sizes, int n_in,
                              void* d_out, int out_size) {
    const float* u = (const float*)d_in[0];  // [B,N,I]
    const float* W = (const float*)d_in[1];  // [C,N,I,O]
    float* out = (float*)d_out;              // [C,B,1,1,O]

    uhat_kernel<<<dim3(Nn / 128, Bb / 64, Cc), 256>>>(u, W);
    routing_kernel<<<dim3(Bb, Cc), 256>>>(out);
}